// round 14
// baseline (speedup 1.0000x reference)
#include <cuda_runtime.h>
#include <cstdint>

#define CH    256
#define FF    512
#define NB    2048
#define BATCH 8
#define BN_COUNT 16384.0f
#define NCTAS 128u
#define NTHREADS 512

#define MT 128
#define NT 256
#define KC 32
#define A_STRIDE 40         // floats per A-chunk row (40%32==8: conflict-free LDS.64)
#define B_STRIDE 264        // floats per B row (bank 8t+r: bijective)

#define A_BUF_FL   (128 * A_STRIDE)         // 5120 floats per chunk buf
#define B_BUF_FL   (KC * B_STRIDE)          // 8448 floats per chunk buf
#define OFF_B      0
#define OFF_A      (2 * B_BUF_FL)           // 16896
#define OFF_RED    48000
#define OFF_BOUT   48256
#define OFF_GAMMA  48512
#define OFF_BETA   48768
#define SMEM_FL    49024
#define SMEM_BYTES (SMEM_FL * 4)            // 196096 B

// phase-0 scratch: overlaps the A region + beyond (A loads start after barrier 1)
#define P0_WOUT   16896             // [16][516]  = 8256  -> 25152
#define P0_WV     25152             // [512][36]  = 18432 -> 43584
#define P0_PART   43584             // [8][512]   = 4096  -> 47680 (< 48000)

// Scratch globals (module-load zeroed; g_sum/g_sumsq re-zeroed per launch
// by bid 0 in phase 0, sequenced by grid barrier 1 before any atomics)
__device__ float    g_Weff[CH * CH];        // column-PERMUTED layout (paired K)
__device__ float    g_sum  [CH];
__device__ float    g_sumsq[CH];
__device__ unsigned g_bar;                  // monotonic ticket counter

__device__ __forceinline__ uint32_t smem_u32(const void* p) {
    uint32_t a;
    asm("{ .reg .u64 t; cvta.to.shared.u64 t, %1; cvt.u32.u64 %0, t; }" : "=r"(a) : "l"(p));
    return a;
}
__device__ __forceinline__ void cp_async16(uint32_t dst, const void* src) {
    asm volatile("cp.async.cg.shared.global [%0], [%1], 16;" :: "r"(dst), "l"(src));
}
__device__ __forceinline__ void cp_commit() {
    asm volatile("cp.async.commit_group;");
}
__device__ __forceinline__ void mma_tf32(float* d, const uint32_t* a, const uint32_t* b) {
    asm volatile(
        "mma.sync.aligned.m16n8k8.row.col.f32.tf32.tf32.f32 "
        "{%0,%1,%2,%3}, {%4,%5,%6,%7}, {%8,%9}, {%0,%1,%2,%3};"
        : "+f"(d[0]), "+f"(d[1]), "+f"(d[2]), "+f"(d[3])
        : "r"(a[0]), "r"(a[1]), "r"(a[2]), "r"(a[3]), "r"(b[0]), "r"(b[1]));
}

// Monotonic grid barrier: no reset, generation from ticket value.
__device__ __forceinline__ void grid_barrier(int tid) {
    __syncthreads();
    if (tid == 0) {
        __threadfence();
        unsigned tck = atomicAdd(&g_bar, 1u);
        unsigned target = (tck & ~(NCTAS - 1u)) + NCTAS;
        unsigned v;
        do {
            asm volatile("ld.acquire.gpu.u32 %0, [%1];" : "=r"(v) : "l"(&g_bar));
        } while ((int)(v - target) < 0);
    }
    __syncthreads();
}

// Paired-K column permutation: within each 8-block, k -> (k%4)*2 + k/4
__device__ __forceinline__ int permc(int c) {
    return (c & ~7) | ((c & 3) << 1) | ((c >> 2) & 1);
}

// ---------------------------------------------------------------------------
// THE kernel. grid 128 (1/SM), 512 threads (16 warps).
// Entry: stage bout/gamma/beta to smem. Phase 0: smem-tiled W_eff mini-GEMM
// (+ bid0 zeroes BN sums). Barrier. Mainloop: BOTH A and B streamed in
// double-buffered 32-K cp.async chunks, fully unrolled tf32 mma. Epi 1:
// y -> acc, quad-reduced smem partials, one global atomic per channel slot.
// Barrier. Per-CTA scale/bias once into smem. Epi 2: normalize, store.
// ---------------------------------------------------------------------------
__global__ void __launch_bounds__(NTHREADS, 1)
mega_kernel(const float* __restrict__ x,
            const float* __restrict__ Wv,
            const float* __restrict__ Wout,
            const float* __restrict__ bout,
            const float* __restrict__ gamma,
            const float* __restrict__ beta,
            float* __restrict__ out) {
    extern __shared__ float smf[];
    uint32_t smb = smem_u32(smf);

    int tid  = threadIdx.x;
    int bid  = blockIdx.x;
    int wid  = tid >> 5;           // 0..15
    int lane = tid & 31;
    int r    = lane >> 2;          // 0..7
    int t    = lane & 3;           // 0..3
    int wRow = wid & 3;            // m * 32
    int wCol = wid >> 2;           // n * 64 (0..3)

    int xt    = bid & 7;
    int yt    = (bid >> 3) & 1;
    int zt    = bid >> 4;
    int n0    = xt * NT;
    int mBase = yt * MT;
    const float* xb = x   + zt * (CH * NB);
    float*       ob = out + zt * (CH * NB);

    // ---- stage per-channel scalars into smem (overlaps phase 0) ----
    if (tid < 64)
        *(float4*)&smf[OFF_BOUT + tid * 4]  = *(const float4*)&bout [tid * 4];
    else if (tid < 128)
        *(float4*)&smf[OFF_GAMMA + (tid - 64) * 4] = *(const float4*)&gamma[(tid - 64) * 4];
    else if (tid < 192)
        *(float4*)&smf[OFF_BETA + (tid - 128) * 4] = *(const float4*)&beta [(tid - 128) * 4];

    // ---- hoisted load bases ----
    const float* bsrc0 = xb + (tid >> 6) * NB + n0 + (tid & 63) * 4;
    uint32_t     bdst0 = smb + (OFF_B + (tid >> 6) * B_STRIDE + (tid & 63) * 4) * 4;
    const float* asrc0 = &g_Weff[(mBase + (tid >> 3)) * CH + (tid & 7) * 4];
    uint32_t     adst0 = smb + (OFF_A + (tid >> 3) * A_STRIDE + (tid & 7) * 4) * 4;

    #define LOAD_B(buf, k0)                                                    \
    {                                                                          \
        _Pragma("unroll")                                                      \
        for (int it = 0; it < 4; it++)                                         \
            cp_async16(bdst0 + (buf) * (B_BUF_FL * 4) + it * (8 * B_STRIDE * 4),\
                       bsrc0 + (k0 + it * 8) * NB);                            \
    }
    #define LOAD_A(buf, ci)                                                    \
    {                                                                          \
        _Pragma("unroll")                                                      \
        for (int it = 0; it < 2; it++)                                         \
            cp_async16(adst0 + (buf) * (A_BUF_FL * 4) + it * (64 * A_STRIDE * 4),\
                       asrc0 + (ci) * 32 + it * (64 * CH));                    \
    }

    LOAD_B(0, 0);
    cp_commit();                    // B0 streams during phase 0

    // ---- Phase 0: W_eff slice (16 o x 32 c per CTA), smem-tiled GEMM ----
    {
        int o0 = ((bid >> 3) & 15) * 16;
        int c0 = (bid & 7) * 32;
        float* wout_s = smf + P0_WOUT;     // [16][516]
        float* wv_s   = smf + P0_WV;       // [512][36]
        float* part_s = smf + P0_PART;     // [8][512]

        if (bid == 0) {
            if (tid < 256)      g_sum  [tid]       = 0.f;
            else                g_sumsq[tid - 256] = 0.f;
        }

        #pragma unroll
        for (int it = 0; it < 4; it++) {
            int e = tid + it * NTHREADS;
            int o = e >> 7, k4 = e & 127;
            *(float4*)&wout_s[o * 516 + k4 * 4] =
                *(const float4*)&Wout[(o0 + o) * FF + k4 * 4];
        }
        #pragma unroll
        for (int it = 0; it < 8; it++) {
            int e = tid + it * NTHREADS;
            int k = e >> 3, c4 = e & 7;
            *(float4*)&wv_s[k * 36 + c4 * 4] =
                *(const float4*)&Wv[k * CH + c0 + c4 * 4];
        }
        __syncthreads();

        int ks = tid >> 6;             // 0..7 K-slice
        int oc = (tid >> 3) & 7;       // 0..7 -> o pair
        int cc = tid & 7;              // 0..7 -> c quad
        float a0[4] = {0.f, 0.f, 0.f, 0.f};
        float a1[4] = {0.f, 0.f, 0.f, 0.f};
        const float* w0p = &wout_s[(oc * 2 + 0) * 516];
        const float* w1p = &wout_s[(oc * 2 + 1) * 516];
        #pragma unroll 8
        for (int k = ks * 64; k < ks * 64 + 64; k++) {
            float4 v = *(const float4*)&wv_s[k * 36 + cc * 4];
            float w0 = w0p[k], w1 = w1p[k];
            a0[0] = fmaf(w0, v.x, a0[0]);
            a0[1] = fmaf(w0, v.y, a0[1]);
            a0[2] = fmaf(w0, v.z, a0[2]);
            a0[3] = fmaf(w0, v.w, a0[3]);
            a1[0] = fmaf(w1, v.x, a1[0]);
            a1[1] = fmaf(w1, v.y, a1[1]);
            a1[2] = fmaf(w1, v.z, a1[2]);
            a1[3] = fmaf(w1, v.w, a1[3]);
        }
        *(float4*)&part_s[ks * 512 + (oc * 2 + 0) * 32 + cc * 4] =
            make_float4(a0[0], a0[1], a0[2], a0[3]);
        *(float4*)&part_s[ks * 512 + (oc * 2 + 1) * 32 + cc * 4] =
            make_float4(a1[0], a1[1], a1[2], a1[3]);
        __syncthreads();

        {
            int o = tid >> 5, c = tid & 31;
            float s = 0.f;
            #pragma unroll
            for (int j = 0; j < 8; j++) s += part_s[j * 512 + tid];
            g_Weff[(o0 + o) * CH + permc(c0 + c)] = s;
        }
    }
    grid_barrier(tid);              // W_eff + zeroed sums globally visible

    LOAD_A(0, 0);
    cp_commit();                    // A0 (20KB) — only exposed prologue load

    if (tid < 256) smf[OFF_RED + tid] = 0.f;

    float acc[2][8][4];
    #pragma unroll
    for (int mt = 0; mt < 2; mt++)
        #pragma unroll
        for (int nt = 0; nt < 8; nt++)
            #pragma unroll
            for (int q = 0; q < 4; q++) acc[mt][nt][q] = 0.f;

    // hoisted fragment base pointers
    const uint2*    aP  = (const uint2*)(smf + OFF_A) + (wRow * 32 + r) * (A_STRIDE / 2) + t;
    const uint32_t* bP0 = (const uint32_t*)(smf + OFF_B) + t * B_STRIDE + wCol * 64 + r;

    // ---- mainloop: 8 K-chunks, A+B both double-buffered, fully unrolled ----
    #pragma unroll
    for (int i = 0; i < 8; i++) {
        int buf = i & 1;
        if (i < 7) {
            LOAD_B((i + 1) & 1, (i + 1) * KC);
            LOAD_A((i + 1) & 1, i + 1);
            cp_commit();
            asm volatile("cp.async.wait_group 1;");
        } else {
            asm volatile("cp.async.wait_group 0;");
        }
        __syncthreads();

        const uint2*    aPb = aP  + buf * (A_BUF_FL / 2);
        const uint32_t* bP  = bP0 + buf * B_BUF_FL;

        #pragma unroll
        for (int kc = 0; kc < 4; kc++) {
            uint32_t afr[2][4];
            #pragma unroll
            for (int mt = 0; mt < 2; mt++) {
                uint2 p0 = aPb[mt * (16 * (A_STRIDE / 2)) + kc * 4];
                uint2 p1 = aPb[mt * (16 * (A_STRIDE / 2)) + 8 * (A_STRIDE / 2) + kc * 4];
                afr[mt][0] = p0.x;
                afr[mt][1] = p1.x;
                afr[mt][2] = p0.y;
                afr[mt][3] = p1.y;
            }
            #pragma unroll
            for (int nt = 0; nt < 8; nt++) {
                uint32_t bfr[2];
                bfr[0] = bP[kc * (8 * B_STRIDE) + nt * 8];
                bfr[1] = bP[kc * (8 * B_STRIDE) + 4 * B_STRIDE + nt * 8];
                mma_tf32(acc[0][nt], afr[0], bfr);
                mma_tf32(acc[1][nt], afr[1], bfr);
            }
        }
        __syncthreads();
    }

    // ---- epilogue 1: fold y into acc, quad-reduced smem partials ----
    float* s_red = smf + OFF_RED;
    #pragma unroll
    for (int mt = 0; mt < 2; mt++) {
        #pragma unroll
        for (int rv = 0; rv < 2; rv++) {
            int rl = wRow * 32 + mt * 16 + rv * 8 + r;
            int rg = mBase + rl;
            float bo = smf[OFF_BOUT + rg];
            int rowOff = rg * NB + n0 + wCol * 64 + t * 2;
            float ps = 0.f, pq = 0.f;
            #pragma unroll
            for (int nt = 0; nt < 8; nt++) {
                float2 xv = *(const float2*)(xb + rowOff + nt * 8);
                float y0 = xv.x + fmaxf(acc[mt][nt][rv * 2 + 0] + bo, 0.f);
                float y1 = xv.y + fmaxf(acc[mt][nt][rv * 2 + 1] + bo, 0.f);
                acc[mt][nt][rv * 2 + 0] = y0;   // acc now holds y
                acc[mt][nt][rv * 2 + 1] = y1;
                ps += y0 + y1;
                pq += y0 * y0 + y1 * y1;
            }
            ps += __shfl_xor_sync(0xFFFFFFFFu, ps, 1);
            ps += __shfl_xor_sync(0xFFFFFFFFu, ps, 2);
            pq += __shfl_xor_sync(0xFFFFFFFFu, pq, 1);
            pq += __shfl_xor_sync(0xFFFFFFFFu, pq, 2);
            if (t == 0) {
                atomicAdd(&s_red[rl], ps);
                atomicAdd(&s_red[128 + rl], pq);
            }
        }
    }
    __syncthreads();
    if (tid < 128)
        atomicAdd(&g_sum[mBase + tid], s_red[tid]);
    else if (tid < 256)
        atomicAdd(&g_sumsq[mBase + (tid - 128)], s_red[tid]);

    grid_barrier(tid);              // all channel sums final

    // ---- per-CTA scale/bias once (tid<128), rest read via LDS ----
    if (tid < 128) {
        int rg = mBase + tid;
        float s = __ldcg(&g_sum[rg]);
        float q = __ldcg(&g_sumsq[rg]);
        float m  = s * (1.0f / BN_COUNT);
        float vv = q * (1.0f / BN_COUNT) - m * m;
        float sc = smf[OFF_GAMMA + rg] * rsqrtf(vv + 1e-5f);
        s_red[tid]       = sc;
        s_red[128 + tid] = smf[OFF_BETA + rg] - m * sc;
    }
    __syncthreads();

    // ---- epilogue 2: normalize register-resident y, single store ----
    #pragma unroll
    for (int mt = 0; mt < 2; mt++) {
        #pragma unroll
        for (int rv = 0; rv < 2; rv++) {
            int rl = wRow * 32 + mt * 16 + rv * 8 + r;
            int rg = mBase + rl;
            float sc = s_red[rl];
            float bi = s_red[128 + rl];
            int rowOff = rg * NB + n0 + wCol * 64 + t * 2;
            #pragma unroll
            for (int nt = 0; nt < 8; nt++) {
                float y0 = acc[mt][nt][rv * 2 + 0];
                float y1 = acc[mt][nt][rv * 2 + 1];
                *(float2*)(ob + rowOff + nt * 8) =
                    make_float2(y0 * sc + bi, y1 * sc + bi);
            }
        }
    }
}

// ---------------------------------------------------------------------------
extern "C" void kernel_launch(void* const* d_in, const int* in_sizes, int n_in,
                              void* d_out, int out_size) {
    const float* x     = (const float*)d_in[0];
    // d_in[1]=Wk, d_in[2]=Wq unused (softmax row-sums == 1 -> agg == V)
    const float* Wv    = (const float*)d_in[3];
    const float* Wout  = (const float*)d_in[4];
    const float* bout  = (const float*)d_in[5];
    const float* gamma = (const float*)d_in[6];
    const float* beta  = (const float*)d_in[7];
    float* out = (float*)d_out;

    cudaFuncSetAttribute(mega_kernel,
                         cudaFuncAttributeMaxDynamicSharedMemorySize, SMEM_BYTES);

    mega_kernel<<<NCTAS, NTHREADS, SMEM_BYTES>>>(x, Wv, Wout, bout, gamma, beta, out);
}

// round 15
// speedup vs baseline: 1.1493x; 1.1493x over previous
#include <cuda_runtime.h>
#include <cuda_bf16.h>
#include <cstdint>

#define CH    256
#define FF    512
#define NB    2048
#define BATCH 8
#define BN_COUNT 16384.0f
#define NCTAS 128u
#define NTHREADS 512

#define MT 128
#define NT 256
#define KC 32                 // K per chunk (bf16: 2 mma-k16 per chunk)

// smem layout in 32-bit units (floats)
#define A_STRIDE_U 40         // u32 units per A row (40%32==8 -> LDS.64 bijective)
#define B_STRIDE_U 20         // u32 units per B row (20r+t mod 32 bijective)
#define A_BUF_U    (128 * A_STRIDE_U)   // 5120
#define B_BUF_U    (256 * B_STRIDE_U)   // 5120
#define OFF_B      0
#define OFF_A      (2 * B_BUF_U)        // 10240
// phase-0 scratch overlaps A region (A loads begin after barrier 1)
#define P0_WOUT    10240               // [16][516]  -> 18496
#define P0_WV      18496               // [512][36]  -> 36928
#define P0_PART    36928               // [8][512]   -> 41024
#define OFF_RED    41024
#define OFF_BOUT   41280
#define OFF_GAMMA  41536
#define OFF_BETA   41792
#define SMEM_FL    42048
#define SMEM_BYTES (SMEM_FL * 4)       // 168192 B

// Scratch globals (module-load zeroed; g_sum/g_sumsq re-zeroed by bid0 in
// phase 0, sequenced by grid barrier 1 before any atomics)
__device__ __align__(16) __nv_bfloat16 g_Weff_bf[CH * CH];      // permuted bf16
__device__ __align__(16) __nv_bfloat16 g_xbf16[64 * 256 * 256]; // [zt*8+xt][n][k]
__device__ float    g_sum  [CH];
__device__ float    g_sumsq[CH];
__device__ unsigned g_bar;

__device__ __forceinline__ uint32_t smem_u32(const void* p) {
    uint32_t a;
    asm("{ .reg .u64 t; cvta.to.shared.u64 t, %1; cvt.u32.u64 %0, t; }" : "=r"(a) : "l"(p));
    return a;
}
__device__ __forceinline__ void cp_async16(uint32_t dst, const void* src) {
    asm volatile("cp.async.cg.shared.global [%0], [%1], 16;" :: "r"(dst), "l"(src));
}
__device__ __forceinline__ void cp_commit() {
    asm volatile("cp.async.commit_group;");
}
__device__ __forceinline__ uint32_t bf16x2(float hi, float lo) {
    uint32_t p;
    asm("cvt.rn.bf16x2.f32 %0, %1, %2;" : "=r"(p) : "f"(hi), "f"(lo));
    return p;
}
__device__ __forceinline__ void mma_bf16(float* d, const uint32_t* a, const uint32_t* b) {
    asm volatile(
        "mma.sync.aligned.m16n8k16.row.col.f32.bf16.bf16.f32 "
        "{%0,%1,%2,%3}, {%4,%5,%6,%7}, {%8,%9}, {%0,%1,%2,%3};"
        : "+f"(d[0]), "+f"(d[1]), "+f"(d[2]), "+f"(d[3])
        : "r"(a[0]), "r"(a[1]), "r"(a[2]), "r"(a[3]), "r"(b[0]), "r"(b[1]));
}

// Monotonic grid barrier: no reset, generation from ticket value.
__device__ __forceinline__ void grid_barrier(int tid) {
    __syncthreads();
    if (tid == 0) {
        __threadfence();
        unsigned tck = atomicAdd(&g_bar, 1u);
        unsigned target = (tck & ~(NCTAS - 1u)) + NCTAS;
        unsigned v;
        do {
            asm volatile("ld.acquire.gpu.u32 %0, [%1];" : "=r"(v) : "l"(&g_bar));
        } while ((int)(v - target) < 0);
    }
    __syncthreads();
}

// ---------------------------------------------------------------------------
// THE kernel. grid 128 (1/SM), 512 threads (16 warps).
// Phase 0: W_eff mini-GEMM -> permuted bf16 global; x -> bf16 [n][k] global
// (yt-split, exactly once per element). Barrier. Mainloop: bf16 m16n8k16,
// A+B double-buffered cp.async (half the LDS/mma of tf32). Epi 1: y->acc +
// one global atomic per channel slot. Barrier. Epi 2: normalize, store.
// ---------------------------------------------------------------------------
__global__ void __launch_bounds__(NTHREADS, 1)
mega_kernel(const float* __restrict__ x,
            const float* __restrict__ Wv,
            const float* __restrict__ Wout,
            const float* __restrict__ bout,
            const float* __restrict__ gamma,
            const float* __restrict__ beta,
            float* __restrict__ out) {
    extern __shared__ float smf[];
    uint32_t smb = smem_u32(smf);

    int tid  = threadIdx.x;
    int bid  = blockIdx.x;
    int lane = tid & 31;
    int wid  = tid >> 5;
    int r    = lane >> 2;
    int t    = lane & 3;
    int wRow = wid & 3;            // m * 32
    int wCol = wid >> 2;           // n * 64 (0..3)

    int xt    = bid & 7;
    int yt    = (bid >> 3) & 1;
    int zt    = bid >> 4;
    int n0    = xt * NT;
    int mBase = yt * MT;
    const float* xb = x   + zt * (CH * NB);
    float*       ob = out + zt * (CH * NB);

    // ---- stage per-channel scalars into smem (overlaps phase 0) ----
    if (tid < 64)
        *(float4*)&smf[OFF_BOUT + tid * 4]  = *(const float4*)&bout [tid * 4];
    else if (tid < 128)
        *(float4*)&smf[OFF_GAMMA + (tid - 64) * 4] = *(const float4*)&gamma[(tid - 64) * 4];
    else if (tid < 192)
        *(float4*)&smf[OFF_BETA + (tid - 128) * 4] = *(const float4*)&beta [(tid - 128) * 4];

    // ---- Phase 0a: W_eff slice (16 o x 32 c per CTA), smem-tiled GEMM ----
    {
        int o0 = ((bid >> 3) & 15) * 16;
        int c0 = (bid & 7) * 32;
        float* wout_s = smf + P0_WOUT;     // [16][516]
        float* wv_s   = smf + P0_WV;       // [512][36]
        float* part_s = smf + P0_PART;     // [8][512]

        if (bid == 0) {
            if (tid < 256)      g_sum  [tid]       = 0.f;
            else                g_sumsq[tid - 256] = 0.f;
        }

        #pragma unroll
        for (int it = 0; it < 4; it++) {
            int e = tid + it * NTHREADS;
            int o = e >> 7, k4 = e & 127;
            *(float4*)&wout_s[o * 516 + k4 * 4] =
                *(const float4*)&Wout[(o0 + o) * FF + k4 * 4];
        }
        #pragma unroll
        for (int it = 0; it < 8; it++) {
            int e = tid + it * NTHREADS;
            int k = e >> 3, c4 = e & 7;
            *(float4*)&wv_s[k * 36 + c4 * 4] =
                *(const float4*)&Wv[k * CH + c0 + c4 * 4];
        }
        __syncthreads();

        int ks = tid >> 6;             // 0..7 K-slice
        int oc = (tid >> 3) & 7;       // 0..7 -> o pair
        int cc = tid & 7;              // 0..7 -> c quad
        float a0[4] = {0.f, 0.f, 0.f, 0.f};
        float a1[4] = {0.f, 0.f, 0.f, 0.f};
        const float* w0p = &wout_s[(oc * 2 + 0) * 516];
        const float* w1p = &wout_s[(oc * 2 + 1) * 516];
        #pragma unroll 8
        for (int k = ks * 64; k < ks * 64 + 64; k++) {
            float4 v = *(const float4*)&wv_s[k * 36 + cc * 4];
            float w0 = w0p[k], w1 = w1p[k];
            a0[0] = fmaf(w0, v.x, a0[0]);
            a0[1] = fmaf(w0, v.y, a0[1]);
            a0[2] = fmaf(w0, v.z, a0[2]);
            a0[3] = fmaf(w0, v.w, a0[3]);
            a1[0] = fmaf(w1, v.x, a1[0]);
            a1[1] = fmaf(w1, v.y, a1[1]);
            a1[2] = fmaf(w1, v.z, a1[2]);
            a1[3] = fmaf(w1, v.w, a1[3]);
        }
        *(float4*)&part_s[ks * 512 + (oc * 2 + 0) * 32 + cc * 4] =
            make_float4(a0[0], a0[1], a0[2], a0[3]);
        *(float4*)&part_s[ks * 512 + (oc * 2 + 1) * 32 + cc * 4] =
            make_float4(a1[0], a1[1], a1[2], a1[3]);
        __syncthreads();

        {
            int o = tid >> 5, c = tid & 31;
            float s = 0.f;
            #pragma unroll
            for (int j = 0; j < 8; j++) s += part_s[j * 512 + tid];
            // store permuted bf16: unit u = cg/2, within-8 perm w->(w%4)*2+w/4
            int cg = c0 + c;
            int u  = cg >> 1;
            int p  = (u & ~7) | (((u & 3) << 1) | ((u >> 2) & 1));
            g_Weff_bf[(o0 + o) * CH + (p << 1) + (cg & 1)] =
                __float2bfloat16_rn(s);
        }
    }

    // ---- Phase 0b: convert own x half-tile to bf16 [n][k] ----
    {
        int cn    = tid & 255;                 // n within tile
        int kbase = mBase + (tid >> 8) * 64;   // yt-split: 128 k per CTA
        const float* xsrc = xb + n0 + cn;
        __nv_bfloat16* xdst =
            g_xbf16 + ((size_t)((zt * 8 + xt) * 256 + cn)) * 256 + kbase;
        #pragma unroll
        for (int g = 0; g < 4; g++) {
            float v[16];
            #pragma unroll
            for (int j = 0; j < 16; j++)
                v[j] = xsrc[(kbase + g * 16 + j) * NB];
            uint32_t pk[8];
            #pragma unroll
            for (int j = 0; j < 8; j++)
                pk[j] = bf16x2(v[2 * j + 1], v[2 * j]);   // lo = even k
            *(uint4*)(xdst + g * 16)     = make_uint4(pk[0], pk[1], pk[2], pk[3]);
            *(uint4*)(xdst + g * 16 + 8) = make_uint4(pk[4], pk[5], pk[6], pk[7]);
        }
    }
    grid_barrier(tid);              // W_eff_bf + g_xbf16 + zeroed sums visible

    // ---- hoisted cp.async bases ----
    const char* asrc0 = (const char*)g_Weff_bf + (mBase + (tid >> 2)) * 512 + (tid & 3) * 16;
    uint32_t    adst0 = smb + (OFF_A + (tid >> 2) * A_STRIDE_U + (tid & 3) * 4) * 4;
    const char* bsrc0 = (const char*)g_xbf16 +
                        ((size_t)((zt * 8 + xt) * 256 + (tid >> 1))) * 512 + (tid & 1) * 32;
    uint32_t    bdst0 = smb + (OFF_B + (tid >> 1) * B_STRIDE_U + (tid & 1) * 8) * 4;

    #define LOAD_AB(buf, i)                                                    \
    {                                                                          \
        cp_async16(adst0 + (buf) * (A_BUF_U * 4), asrc0 + (i) * 64);           \
        cp_async16(bdst0 + (buf) * (B_BUF_U * 4),      bsrc0 + (i) * 64);      \
        cp_async16(bdst0 + (buf) * (B_BUF_U * 4) + 16, bsrc0 + (i) * 64 + 16); \
    }

    LOAD_AB(0, 0);
    cp_commit();

    if (tid < 256) smf[OFF_RED + tid] = 0.f;

    float acc[2][8][4];
    #pragma unroll
    for (int mt = 0; mt < 2; mt++)
        #pragma unroll
        for (int nt = 0; nt < 8; nt++)
            #pragma unroll
            for (int q = 0; q < 4; q++) acc[mt][nt][q] = 0.f;

    // hoisted fragment base pointers
    const uint2*    aP  = (const uint2*)smf + (OFF_A / 2) + (wRow * 32 + r) * (A_STRIDE_U / 2) + t;
    const uint32_t* bP0 = (const uint32_t*)smf + OFF_B + (wCol * 64 + r) * B_STRIDE_U + t;

    // ---- mainloop: 8 K-chunks, bf16 m16n8k16, fully unrolled ----
    #pragma unroll
    for (int i = 0; i < 8; i++) {
        int buf = i & 1;
        if (i < 7) {
            LOAD_AB((i + 1) & 1, i + 1);
            cp_commit();
            asm volatile("cp.async.wait_group 1;");
        } else {
            asm volatile("cp.async.wait_group 0;");
        }
        __syncthreads();

        const uint2*    aPb = aP  + buf * (A_BUF_U / 2);
        const uint32_t* bP  = bP0 + buf * B_BUF_U;

        #pragma unroll
        for (int kc = 0; kc < 2; kc++) {
            uint32_t afr[2][4];
            #pragma unroll
            for (int mt = 0; mt < 2; mt++) {
                uint2 p0 = aPb[mt * (16 * (A_STRIDE_U / 2)) + kc * 4];
                uint2 p1 = aPb[mt * (16 * (A_STRIDE_U / 2)) + 8 * (A_STRIDE_U / 2) + kc * 4];
                afr[mt][0] = p0.x;   // a0 (r,   k 2t..2t+1)
                afr[mt][1] = p1.x;   // a1 (r+8)
                afr[mt][2] = p0.y;   // a2 (r,   k 2t+8..2t+9)
                afr[mt][3] = p1.y;   // a3 (r+8)
            }
            #pragma unroll
            for (int nt = 0; nt < 8; nt++) {
                uint32_t bfr[2];
                bfr[0] = bP[nt * (8 * B_STRIDE_U) + kc * 8];        // b0
                bfr[1] = bP[nt * (8 * B_STRIDE_U) + kc * 8 + 4];    // b1
                mma_bf16(acc[0][nt], afr[0], bfr);
                mma_bf16(acc[1][nt], afr[1], bfr);
            }
        }
        __syncthreads();
    }

    // ---- epilogue 1: fold y into acc (fp32 x), quad-reduced partials ----
    float* s_red = smf + OFF_RED;
    #pragma unroll
    for (int mt = 0; mt < 2; mt++) {
        #pragma unroll
        for (int rv = 0; rv < 2; rv++) {
            int rl = wRow * 32 + mt * 16 + rv * 8 + r;
            int rg = mBase + rl;
            float bo = smf[OFF_BOUT + rg];
            int rowOff = rg * NB + n0 + wCol * 64 + t * 2;
            float ps = 0.f, pq = 0.f;
            #pragma unroll
            for (int nt = 0; nt < 8; nt++) {
                float2 xv = *(const float2*)(xb + rowOff + nt * 8);
                float y0 = xv.x + fmaxf(acc[mt][nt][rv * 2 + 0] + bo, 0.f);
                float y1 = xv.y + fmaxf(acc[mt][nt][rv * 2 + 1] + bo, 0.f);
                acc[mt][nt][rv * 2 + 0] = y0;   // acc now holds y
                acc[mt][nt][rv * 2 + 1] = y1;
                ps += y0 + y1;
                pq += y0 * y0 + y1 * y1;
            }
            ps += __shfl_xor_sync(0xFFFFFFFFu, ps, 1);
            ps += __shfl_xor_sync(0xFFFFFFFFu, ps, 2);
            pq += __shfl_xor_sync(0xFFFFFFFFu, pq, 1);
            pq += __shfl_xor_sync(0xFFFFFFFFu, pq, 2);
            if (t == 0) {
                atomicAdd(&s_red[rl], ps);
                atomicAdd(&s_red[128 + rl], pq);
            }
        }
    }
    __syncthreads();
    if (tid < 128)
        atomicAdd(&g_sum[mBase + tid], s_red[tid]);
    else if (tid < 256)
        atomicAdd(&g_sumsq[mBase + (tid - 128)], s_red[tid]);

    grid_barrier(tid);              // all channel sums final

    // ---- per-CTA scale/bias once (tid<128) ----
    if (tid < 128) {
        int rg = mBase + tid;
        float s = __ldcg(&g_sum[rg]);
        float q = __ldcg(&g_sumsq[rg]);
        float m  = s * (1.0f / BN_COUNT);
        float vv = q * (1.0f / BN_COUNT) - m * m;
        float sc = smf[OFF_GAMMA + rg] * rsqrtf(vv + 1e-5f);
        s_red[tid]       = sc;
        s_red[128 + tid] = smf[OFF_BETA + rg] - m * sc;
    }
    __syncthreads();

    // ---- epilogue 2: normalize register-resident y, single store ----
    #pragma unroll
    for (int mt = 0; mt < 2; mt++) {
        #pragma unroll
        for (int rv = 0; rv < 2; rv++) {
            int rl = wRow * 32 + mt * 16 + rv * 8 + r;
            int rg = mBase + rl;
            float sc = s_red[rl];
            float bi = s_red[128 + rl];
            int rowOff = rg * NB + n0 + wCol * 64 + t * 2;
            #pragma unroll
            for (int nt = 0; nt < 8; nt++) {
                float y0 = acc[mt][nt][rv * 2 + 0];
                float y1 = acc[mt][nt][rv * 2 + 1];
                *(float2*)(ob + rowOff + nt * 8) =
                    make_float2(y0 * sc + bi, y1 * sc + bi);
            }
        }
    }
}

// ---------------------------------------------------------------------------
extern "C" void kernel_launch(void* const* d_in, const int* in_sizes, int n_in,
                              void* d_out, int out_size) {
    const float* x     = (const float*)d_in[0];
    // d_in[1]=Wk, d_in[2]=Wq unused (softmax row-sums == 1 -> agg == V)
    const float* Wv    = (const float*)d_in[3];
    const float* Wout  = (const float*)d_in[4];
    const float* bout  = (const float*)d_in[5];
    const float* gamma = (const float*)d_in[6];
    const float* beta  = (const float*)d_in[7];
    float* out = (float*)d_out;

    cudaFuncSetAttribute(mega_kernel,
                         cudaFuncAttributeMaxDynamicSharedMemorySize, SMEM_BYTES);

    mega_kernel<<<NCTAS, NTHREADS, SMEM_BYTES>>>(x, Wv, Wout, bout, gamma, beta, out);
}